// round 15
// baseline (speedup 1.0000x reference)
#include <cuda_runtime.h>

#define T_STEPS 100
#define BATCH   256
#define D0      784
#define D1      1024
#define D2      256
#define XCAP    112          // uint byte-offset entries per row (mean nnz 39)

#define ALPHA 0.8f
#define BETA  0.95f
#define OMB   0.05f

// layer 1: 16 col-chunks of 64 cols, REP1=4 row-groups -> 64 blocks, 2 rows/warp (balanced)
// layer 2:  8 col-chunks of 32 cols, REP2=8 row-groups -> 64 blocks, 1 row/warp
#define N_CH1 16
#define REP1  4
#define NB_L1 (N_CH1 * REP1)      // 64
#define N_CH2 8
#define REP2  8
#define NB_L2 (N_CH2 * REP2)      // 64
#define NBLOCKS (NB_L1 + NB_L2)   // 128 <= 148 SMs, co-resident
#define NT 1024

// smem: L1: tile 785*64*4 = 200960 + 32 warps * 224 uint staging + 16 pad = 229648
//       L2: 1025*32*4 = 131200 + 32 warps * 520 uint lists = 197760
#define SMEM_BYTES ((D0 + 1) * 64 * 4 + 32 * 224 * 4 + 16)

// prep block ranges
#define NB_TA 800    // W1 transpose tiles
#define NB_TB 256    // W2 transpose tiles
#define NB_XI 3200   // 25600 (t,b) rows / 8
#define NB_IN 256
#define NB_PREP (NB_TA + NB_TB + NB_XI + NB_IN)

// packed f32x2 add: two independent fp32 adds, bit-exact per component
#define ADD2(x, y) asm("add.rn.f32x2 %0, %1, %2;" : "=l"(x) : "l"(x), "l"(y))

// ---------------- device scratch ----------------
__device__ float g_Wt1[(D0 + 1) * D1];               // [k][j], row D0 zeros
__device__ float g_Wt2[(D1 + 1) * D2];               // [k][j], row D1 zeros
__device__ unsigned g_xidx[T_STEPS * BATCH * XCAP];  // byte offsets k*256, fully padded
__device__ int g_xnnz[T_STEPS * BATCH];              // padded-to-4 counts (<= XCAP)
__device__ unsigned g_s1mask[T_STEPS][BATCH][32];    // full history
__device__ int g_done[T_STEPS];

// ---------------- fused prep kernel ----------------
__global__ void prep_all(const float* __restrict__ x,
                         const float* __restrict__ W1,
                         const float* __restrict__ W2,
                         float* __restrict__ out) {
    __shared__ float tts[32][33];
    int bx = blockIdx.x;
    int tid = threadIdx.x;
    int tx = tid & 31, ty = tid >> 5;      // 32 x 8

    if (bx < NB_TA) {
        int kt = bx % 25, jt = bx / 25;
        int k0 = kt * 32, j0 = jt * 32;
        #pragma unroll
        for (int yy = 0; yy < 32; yy += 8) {
            int k = k0 + tx;
            tts[ty + yy][tx] = (k < D0) ? W1[(j0 + ty + yy) * D0 + k] : 0.0f;
        }
        __syncthreads();
        #pragma unroll
        for (int yy = 0; yy < 32; yy += 8) {
            int k = k0 + ty + yy;
            if (k < D0) g_Wt1[k * D1 + j0 + tx] = tts[tx][ty + yy];
        }
    } else if (bx < NB_TA + NB_TB) {
        int b2 = bx - NB_TA;
        int kt = b2 & 31, jt = b2 >> 5;
        int k0 = kt * 32, j0 = jt * 32;
        #pragma unroll
        for (int yy = 0; yy < 32; yy += 8)
            tts[ty + yy][tx] = W2[(j0 + ty + yy) * D1 + k0 + tx];
        __syncthreads();
        #pragma unroll
        for (int yy = 0; yy < 32; yy += 8)
            g_Wt2[(k0 + ty + yy) * D2 + j0 + tx] = tts[tx][ty + yy];
    } else if (bx < NB_TA + NB_TB + NB_XI) {
        int row  = (bx - NB_TA - NB_TB) * 8 + ty;
        int lane = tx;
        const float* xr = x + (size_t)row * D0;
        unsigned* o = g_xidx + (size_t)row * XCAP;
        int base = 0;
        #pragma unroll 1
        for (int c = 0; c < 25; ++c) {
            int i = c * 32 + lane;
            bool p = (i < D0) && (xr[i] != 0.0f);
            unsigned m = __ballot_sync(0xffffffffu, p);
            if (p) {
                int pos = base + __popc(m & ((1u << lane) - 1u));
                if (pos < XCAP) o[pos] = (unsigned)(i << 8);   // k * 256 bytes
            }
            base += __popc(m);
        }
        int total = base > XCAP ? XCAP : base;
        for (int q = total + lane; q < XCAP; q += 32)
            o[q] = (unsigned)(D0 << 8);                        // zero-row pad
        if (lane == 0) {
            int nnzp = (total + 3) & ~3;
            if (nnzp > XCAP) nnzp = XCAP;
            g_xnnz[row] = nnzp;
        }
    } else {
        int i = (bx - NB_TA - NB_TB - NB_XI) * 256 + tid;
        if (i < BATCH * D2) out[i] = 0.0f;
        if (i < BATCH * 32) ((unsigned*)g_s1mask)[i] = 0u;
        if (i < T_STEPS) g_done[i] = (i == 0) ? NB_L1 : 0;
        if (i < D1) g_Wt1[D0 * D1 + i] = 0.0f;
        if (i < D2) g_Wt2[D1 * D2 + i] = 0.0f;
    }
}

// bit-expand 16-bit value to even bit positions of a 32-bit value
__device__ __forceinline__ unsigned expand16(unsigned v) {
    v &= 0xFFFFu;
    v = (v | (v << 8)) & 0x00FF00FFu;
    v = (v | (v << 4)) & 0x0F0F0F0Fu;
    v = (v | (v << 2)) & 0x33333333u;
    v = (v | (v << 1)) & 0x55555555u;
    return v;
}

// ---------------- persistent SNN kernel (flag-synced) ----------------
__global__ void __launch_bounds__(NT, 1)
snn_persistent(float* __restrict__ out) {
    extern __shared__ float tile[];
    const unsigned FULL = 0xffffffffu;
    int tid  = threadIdx.x;
    int warp = tid >> 5;
    int lane = tid & 31;
    int bx   = blockIdx.x;

    if (bx < NB_L1) {
        // ===== layer 1 (producer): 64-col chunk, every warp exactly 2 rows =====
        int ch  = bx & (N_CH1 - 1);
        int rep = bx >> 4;
        int jb  = ch * 64;
        for (int k = warp; k < D0 + 1; k += 32) {
            tile[k * 64 + lane]      = g_Wt1[k * D1 + jb + lane];
            tile[k * 64 + 32 + lane] = g_Wt1[k * D1 + jb + 32 + lane];
        }
        // per-warp staging: 224 uints (A:0..111, B:112..223)
        unsigned* stA = (unsigned*)(tile + (D0 + 1) * 64) + warp * 224;
        unsigned* stB = stA + XCAP;

        int r0   = rep * 64;
        int rowA = r0 + warp;
        int rowB = r0 + 32 + warp;
        unsigned long long accA, accB, Ia = 0ull, Va = 0ull, Ib = 0ull, Vb = 0ull;
        const char* tb = (const char*)tile;
        int lane8 = lane << 3;
        __syncthreads();

        #pragma unroll 1
        for (int t = 1; t < T_STEPS; ++t) {
            int xrA = (t - 1) * BATCH + rowA;
            int xrB = (t - 1) * BATCH + rowB;
            int nA = __ldg(&g_xnnz[xrA]);
            int nB = __ldg(&g_xnnz[xrB]);
            const uint4* lstA4 = (const uint4*)(g_xidx + (size_t)xrA * XCAP);
            const uint4* lstB4 = (const uint4*)(g_xidx + (size_t)xrB * XCAP);
            if (lane < 28) {
                ((uint4*)stA)[lane] = __ldg(lstA4 + lane);
                ((uint4*)stB)[lane] = __ldg(lstB4 + lane);
            }
            __syncwarp();

            int nmax = nA > nB ? nA : nB;
            accA = 0ull; accB = 0ull;
            // software-pipelined: index uint4 for iteration i+1 prefetched during i
            uint4 oa = *(const uint4*)(stA);
            uint4 ob = *(const uint4*)(stB);
            #pragma unroll 1
            for (int i = 0; i < nmax; i += 4) {
                uint4 na = *(const uint4*)(stA + i + 4);   // prefetch (addr data-indep)
                uint4 nb = *(const uint4*)(stB + i + 4);
                unsigned long long a0 = *(const unsigned long long*)(tb + oa.x + lane8);
                unsigned long long a1 = *(const unsigned long long*)(tb + oa.y + lane8);
                unsigned long long a2 = *(const unsigned long long*)(tb + oa.z + lane8);
                unsigned long long a3 = *(const unsigned long long*)(tb + oa.w + lane8);
                unsigned long long b0 = *(const unsigned long long*)(tb + ob.x + lane8);
                unsigned long long b1 = *(const unsigned long long*)(tb + ob.y + lane8);
                unsigned long long b2 = *(const unsigned long long*)(tb + ob.z + lane8);
                unsigned long long b3 = *(const unsigned long long*)(tb + ob.w + lane8);
                ADD2(accA, a0); ADD2(accA, a1); ADD2(accA, a2); ADD2(accA, a3);
                ADD2(accB, b0); ADD2(accB, b1); ADD2(accB, b2); ADD2(accB, b3);
                oa = na; ob = nb;
            }

            // LIF row A (unpack, exact per-component fp32)
            {
                float ax, ay, ix, iy, vx, vy;
                asm("mov.b64 {%0,%1}, %2;" : "=f"(ax), "=f"(ay) : "l"(accA));
                asm("mov.b64 {%0,%1}, %2;" : "=f"(ix), "=f"(iy) : "l"(Ia));
                asm("mov.b64 {%0,%1}, %2;" : "=f"(vx), "=f"(vy) : "l"(Va));
                ix = ALPHA * ix + ax;  iy = ALPHA * iy + ay;
                float vpx = BETA * vx + OMB * ix, vpy = BETA * vy + OMB * iy;
                bool s0 = vpx > 1.0f, s1 = vpy > 1.0f;
                vx = s0 ? 0.f : vpx;  vy = s1 ? 0.f : vpy;
                asm("mov.b64 %0, {%1,%2};" : "=l"(Ia) : "f"(ix), "f"(iy));
                asm("mov.b64 %0, {%1,%2};" : "=l"(Va) : "f"(vx), "f"(vy));
                unsigned be = __ballot_sync(FULL, s0);
                unsigned bo = __ballot_sync(FULL, s1);
                if (lane == 0) {
                    unsigned w0 = expand16(be) | (expand16(bo) << 1);
                    unsigned w1 = expand16(be >> 16) | (expand16(bo >> 16) << 1);
                    *(unsigned long long*)&g_s1mask[t][rowA][2 * ch] =
                        (unsigned long long)w0 | ((unsigned long long)w1 << 32);
                }
            }
            // LIF row B
            {
                float ax, ay, ix, iy, vx, vy;
                asm("mov.b64 {%0,%1}, %2;" : "=f"(ax), "=f"(ay) : "l"(accB));
                asm("mov.b64 {%0,%1}, %2;" : "=f"(ix), "=f"(iy) : "l"(Ib));
                asm("mov.b64 {%0,%1}, %2;" : "=f"(vx), "=f"(vy) : "l"(Vb));
                ix = ALPHA * ix + ax;  iy = ALPHA * iy + ay;
                float vpx = BETA * vx + OMB * ix, vpy = BETA * vy + OMB * iy;
                bool s0 = vpx > 1.0f, s1 = vpy > 1.0f;
                vx = s0 ? 0.f : vpx;  vy = s1 ? 0.f : vpy;
                asm("mov.b64 %0, {%1,%2};" : "=l"(Ib) : "f"(ix), "f"(iy));
                asm("mov.b64 %0, {%1,%2};" : "=l"(Vb) : "f"(vx), "f"(vy));
                unsigned be = __ballot_sync(FULL, s0);
                unsigned bo = __ballot_sync(FULL, s1);
                if (lane == 0) {
                    unsigned w0 = expand16(be) | (expand16(bo) << 1);
                    unsigned w1 = expand16(be >> 16) | (expand16(bo >> 16) << 1);
                    *(unsigned long long*)&g_s1mask[t][rowB][2 * ch] =
                        (unsigned long long)w0 | ((unsigned long long)w1 << 32);
                }
            }
            if (lane == 0) __threadfence();   // release mask writes
            __syncthreads();
            if (tid == 0) atomicAdd(&g_done[t], 1);
        }
    } else {
        // ===== layer 2 (consumer): 32-col chunk, warp = one batch row =====
        int bi  = bx - NB_L1;
        int ch  = bi & (N_CH2 - 1);
        int rep = bi >> 3;
        int jb  = ch * 32;
        for (int k = warp; k < D1 + 1; k += 32)
            tile[k * 32 + lane] = g_Wt2[k * D2 + jb + lane];
        unsigned* mylist = (unsigned*)((char*)tile + (D1 + 1) * 32 * 4) + warp * 520;
        int row = rep * 32 + warp;
        float I = 0.f, V = 0.f;
        const char* tb = (const char*)tile;
        int lane4 = lane << 2;
        __syncthreads();

        #pragma unroll 1
        for (int t = 1; t < T_STEPS; ++t) {
            if (tid == 0) {
                volatile int* dp = g_done + (t - 1);
                while (*dp < NB_L1) { }
                __threadfence();
            }
            __syncthreads();

            unsigned mword = __ldcg(&g_s1mask[t - 1][row][lane]);
            float acc = 0.f;
            #pragma unroll 1
            for (int p = 0; p < 2; ++p) {
                unsigned wv = __shfl_sync(FULL, mword, (p << 4) + (lane >> 1));
                unsigned bits = (wv >> ((lane & 1) << 4)) & 0xffffu;
                int cnt = __popc(bits);
                int incl = cnt;
                #pragma unroll
                for (int o = 1; o < 32; o <<= 1) {
                    int v = __shfl_up_sync(FULL, incl, o);
                    if (lane >= o) incl += v;
                }
                int base  = incl - cnt;
                int total = __shfl_sync(FULL, incl, 31);
                int kb = (((p << 4) + (lane >> 1)) << 5) + ((lane & 1) << 4);
                int off = base;
                while (bits) {
                    int b = __ffs(bits) - 1;
                    bits &= bits - 1;
                    mylist[off++] = (unsigned)((kb + b) << 7);   // byte offset k*128
                }
                int totp = (total + 3) & ~3;
                for (int q = total + lane; q < totp; q += 32)
                    mylist[q] = (unsigned)(D1 << 7);             // zero-row pad
                __syncwarp();

                // software-pipelined gather
                uint4 o4 = *(const uint4*)(mylist);
                #pragma unroll 1
                for (int i = 0; i < totp; i += 4) {
                    uint4 nx = *(const uint4*)(mylist + i + 4);  // prefetch
                    acc += *(const float*)(tb + o4.x + lane4);
                    acc += *(const float*)(tb + o4.y + lane4);
                    acc += *(const float*)(tb + o4.z + lane4);
                    acc += *(const float*)(tb + o4.w + lane4);
                    o4 = nx;
                }
                __syncwarp();
            }

            I = ALPHA * I + acc;
            float Vp = BETA * V + OMB * I;
            bool s = Vp > 1.0f;
            V = s ? 0.f : Vp;
            out[t * (BATCH * D2) + row * D2 + jb + lane] = s ? 1.0f : 0.0f;
        }
    }
}

// ---------------- launch ----------------
extern "C" void kernel_launch(void* const* d_in, const int* in_sizes, int n_in,
                              void* d_out, int out_size) {
    const float *x = nullptr, *W1 = nullptr, *W2 = nullptr;
    for (int i = 0; i < n_in; ++i) {
        if      (in_sizes[i] == T_STEPS * BATCH * D0) x  = (const float*)d_in[i];
        else if (in_sizes[i] == D1 * D0)              W1 = (const float*)d_in[i];
        else if (in_sizes[i] == D2 * D1)              W2 = (const float*)d_in[i];
    }
    float* out = (float*)d_out;

    static int smem_set = 0;
    if (!smem_set) {
        cudaFuncSetAttribute(snn_persistent,
                             cudaFuncAttributeMaxDynamicSharedMemorySize, SMEM_BYTES);
        smem_set = 1;
    }

    prep_all<<<NB_PREP, 256>>>(x, W1, W2, out);
    snn_persistent<<<NBLOCKS, NT, SMEM_BYTES>>>(out);
}

// round 17
// speedup vs baseline: 1.1728x; 1.1728x over previous
#include <cuda_runtime.h>

#define T_STEPS 100
#define BATCH   256
#define D0      784
#define D1      1024
#define D2      256
#define XCAP    112          // uint byte-offset entries per row (mean nnz 39)

#define ALPHA 0.8f
#define BETA  0.95f
#define OMB   0.05f

// layer 1: 16 col-chunks of 64 cols, REP1=5 row-groups -> 80 blocks
// layer 2:  8 col-chunks of 32 cols, REP2=8 row-groups -> 64 blocks, warp = one row-chunk
#define N_CH1 16
#define REP1  5
#define NB_L1 (N_CH1 * REP1)      // 80
#define N_CH2 8
#define REP2  8
#define NB_L2 (N_CH2 * REP2)      // 64
#define NBLOCKS (NB_L1 + NB_L2)   // 144 <= 148 SMs, co-resident
#define NT 1024

// smem: L1: tile 785*64*4 = 200960 + 32 warps * 224 uint staging + 16 pad = 229648
//       L2: 1025*32*4 = 131200 + 32 warps * 520 uint lists = 197760
#define SMEM_BYTES ((D0 + 1) * 64 * 4 + 32 * 224 * 4 + 16)

// prep block ranges
#define NB_TA 800    // W1 transpose tiles
#define NB_TB 256    // W2 transpose tiles
#define NB_XI 3200   // 25600 (t,b) rows / 8
#define NB_IN 256
#define NB_PREP (NB_TA + NB_TB + NB_XI + NB_IN)

// packed f32x2 add: two independent fp32 adds, bit-exact per component
#define ADD2(x, y) asm("add.rn.f32x2 %0, %1, %2;" : "=l"(x) : "l"(x), "l"(y))

// ---------------- device scratch ----------------
__device__ float g_Wt1[(D0 + 1) * D1];               // [k][j], row D0 zeros
__device__ float g_Wt2[(D1 + 1) * D2];               // [k][j], row D1 zeros
__device__ unsigned g_xidx[T_STEPS * BATCH * XCAP];  // byte offsets k*256, fully padded
__device__ int g_xnnz[T_STEPS * BATCH];              // padded-to-4 counts (<= XCAP)
__device__ unsigned g_s1mask[T_STEPS][BATCH][32];    // full history
__device__ int g_rowcnt[T_STEPS][BATCH];             // # chunks published per (t,row)

// ---------------- fused prep kernel ----------------
__global__ void prep_all(const float* __restrict__ x,
                         const float* __restrict__ W1,
                         const float* __restrict__ W2,
                         float* __restrict__ out) {
    __shared__ float tts[32][33];
    int bx = blockIdx.x;
    int tid = threadIdx.x;
    int tx = tid & 31, ty = tid >> 5;      // 32 x 8

    if (bx < NB_TA) {
        int kt = bx % 25, jt = bx / 25;
        int k0 = kt * 32, j0 = jt * 32;
        #pragma unroll
        for (int yy = 0; yy < 32; yy += 8) {
            int k = k0 + tx;
            tts[ty + yy][tx] = (k < D0) ? W1[(j0 + ty + yy) * D0 + k] : 0.0f;
        }
        __syncthreads();
        #pragma unroll
        for (int yy = 0; yy < 32; yy += 8) {
            int k = k0 + ty + yy;
            if (k < D0) g_Wt1[k * D1 + j0 + tx] = tts[tx][ty + yy];
        }
    } else if (bx < NB_TA + NB_TB) {
        int b2 = bx - NB_TA;
        int kt = b2 & 31, jt = b2 >> 5;
        int k0 = kt * 32, j0 = jt * 32;
        #pragma unroll
        for (int yy = 0; yy < 32; yy += 8)
            tts[ty + yy][tx] = W2[(j0 + ty + yy) * D1 + k0 + tx];
        __syncthreads();
        #pragma unroll
        for (int yy = 0; yy < 32; yy += 8)
            g_Wt2[(k0 + ty + yy) * D2 + j0 + tx] = tts[tx][ty + yy];
    } else if (bx < NB_TA + NB_TB + NB_XI) {
        int row  = (bx - NB_TA - NB_TB) * 8 + ty;
        int lane = tx;
        const float* xr = x + (size_t)row * D0;
        unsigned* o = g_xidx + (size_t)row * XCAP;
        int base = 0;
        #pragma unroll 1
        for (int c = 0; c < 25; ++c) {
            int i = c * 32 + lane;
            bool p = (i < D0) && (xr[i] != 0.0f);
            unsigned m = __ballot_sync(0xffffffffu, p);
            if (p) {
                int pos = base + __popc(m & ((1u << lane) - 1u));
                if (pos < XCAP) o[pos] = (unsigned)(i << 8);   // k * 256 bytes
            }
            base += __popc(m);
        }
        int total = base > XCAP ? XCAP : base;
        for (int q = total + lane; q < XCAP; q += 32)
            o[q] = (unsigned)(D0 << 8);                        // zero-row pad
        if (lane == 0) {
            int nnzp = (total + 3) & ~3;
            if (nnzp > XCAP) nnzp = XCAP;
            g_xnnz[row] = nnzp;
        }
    } else {
        int i = (bx - NB_TA - NB_TB - NB_XI) * 256 + tid;
        if (i < BATCH * D2) out[i] = 0.0f;
        if (i < BATCH * 32) ((unsigned*)g_s1mask)[i] = 0u;       // masks at t=0
        if (i < T_STEPS * BATCH)
            ((int*)g_rowcnt)[i] = (i < BATCH) ? N_CH1 : 0;       // t=0 pre-published
        if (i < D1) g_Wt1[D0 * D1 + i] = 0.0f;
        if (i < D2) g_Wt2[D1 * D2 + i] = 0.0f;
    }
}

// bit-expand 16-bit value to even bit positions of a 32-bit value
__device__ __forceinline__ unsigned expand16(unsigned v) {
    v &= 0xFFFFu;
    v = (v | (v << 8)) & 0x00FF00FFu;
    v = (v | (v << 4)) & 0x0F0F0F0Fu;
    v = (v | (v << 2)) & 0x33333333u;
    v = (v | (v << 1)) & 0x55555555u;
    return v;
}

// ---------------- persistent SNN kernel: async warp-level dataflow ----------------
__global__ void __launch_bounds__(NT, 1)
snn_persistent(float* __restrict__ out) {
    extern __shared__ float tile[];
    const unsigned FULL = 0xffffffffu;
    int tid  = threadIdx.x;
    int warp = tid >> 5;
    int lane = tid & 31;
    int bx   = blockIdx.x;

    if (bx < NB_L1) {
        // ===== layer 1 (producer, free-running warps): 64-col chunk =====
        int ch  = bx & (N_CH1 - 1);
        int rep = bx >> 4;
        int jb  = ch * 64;
        for (int k = warp; k < D0 + 1; k += 32) {
            tile[k * 64 + lane]      = g_Wt1[k * D1 + jb + lane];
            tile[k * 64 + 32 + lane] = g_Wt1[k * D1 + jb + 32 + lane];
        }
        unsigned* stA = (unsigned*)(tile + (D0 + 1) * 64) + warp * 224;
        unsigned* stB = stA + XCAP;

        int r0 = (rep * BATCH) / REP1, r1 = ((rep + 1) * BATCH) / REP1;
        int rowA = r0 + warp;                    // always valid (r1-r0 >= 51)
        int rowB = r0 + 32 + warp;
        bool hasB = (32 + warp) < (r1 - r0);
        unsigned long long accA, accB, Ia = 0ull, Va = 0ull, Ib = 0ull, Vb = 0ull;
        const char* tb = (const char*)tile;
        int lane8 = lane << 3;
        __syncthreads();                          // tile ready; warps free-run from here

        #pragma unroll 1
        for (int t = 1; t < T_STEPS; ++t) {
            int xrA = (t - 1) * BATCH + rowA;
            int nA = __ldg(&g_xnnz[xrA]);
            const uint4* lstA4 = (const uint4*)(g_xidx + (size_t)xrA * XCAP);
            if (lane < 28) ((uint4*)stA)[lane] = __ldg(lstA4 + lane);

            if (hasB) {
                int xrB = (t - 1) * BATCH + rowB;
                int nB = __ldg(&g_xnnz[xrB]);
                const uint4* lstB4 = (const uint4*)(g_xidx + (size_t)xrB * XCAP);
                if (lane < 28) ((uint4*)stB)[lane] = __ldg(lstB4 + lane);
                __syncwarp();

                int nmax = nA > nB ? nA : nB;
                accA = 0ull; accB = 0ull;
                #pragma unroll 1
                for (int i = 0; i < nmax; i += 4) {
                    uint4 oa = *(const uint4*)(stA + i);    // LDS.128 broadcast
                    uint4 ob = *(const uint4*)(stB + i);
                    unsigned long long a0 = *(const unsigned long long*)(tb + oa.x + lane8);
                    unsigned long long a1 = *(const unsigned long long*)(tb + oa.y + lane8);
                    unsigned long long a2 = *(const unsigned long long*)(tb + oa.z + lane8);
                    unsigned long long a3 = *(const unsigned long long*)(tb + oa.w + lane8);
                    unsigned long long b0 = *(const unsigned long long*)(tb + ob.x + lane8);
                    unsigned long long b1 = *(const unsigned long long*)(tb + ob.y + lane8);
                    unsigned long long b2 = *(const unsigned long long*)(tb + ob.z + lane8);
                    unsigned long long b3 = *(const unsigned long long*)(tb + ob.w + lane8);
                    ADD2(accA, a0); ADD2(accA, a1); ADD2(accA, a2); ADD2(accA, a3);
                    ADD2(accB, b0); ADD2(accB, b1); ADD2(accB, b2); ADD2(accB, b3);
                }
            } else {
                __syncwarp();
                accA = 0ull;
                #pragma unroll 1
                for (int i = 0; i < nA; i += 4) {
                    uint4 oa = *(const uint4*)(stA + i);
                    unsigned long long a0 = *(const unsigned long long*)(tb + oa.x + lane8);
                    unsigned long long a1 = *(const unsigned long long*)(tb + oa.y + lane8);
                    unsigned long long a2 = *(const unsigned long long*)(tb + oa.z + lane8);
                    unsigned long long a3 = *(const unsigned long long*)(tb + oa.w + lane8);
                    ADD2(accA, a0); ADD2(accA, a1); ADD2(accA, a2); ADD2(accA, a3);
                }
            }

            // LIF row A
            {
                float ax, ay, ix, iy, vx, vy;
                asm("mov.b64 {%0,%1}, %2;" : "=f"(ax), "=f"(ay) : "l"(accA));
                asm("mov.b64 {%0,%1}, %2;" : "=f"(ix), "=f"(iy) : "l"(Ia));
                asm("mov.b64 {%0,%1}, %2;" : "=f"(vx), "=f"(vy) : "l"(Va));
                ix = ALPHA * ix + ax;  iy = ALPHA * iy + ay;
                float vpx = BETA * vx + OMB * ix, vpy = BETA * vy + OMB * iy;
                bool s0 = vpx > 1.0f, s1 = vpy > 1.0f;
                vx = s0 ? 0.f : vpx;  vy = s1 ? 0.f : vpy;
                asm("mov.b64 %0, {%1,%2};" : "=l"(Ia) : "f"(ix), "f"(iy));
                asm("mov.b64 %0, {%1,%2};" : "=l"(Va) : "f"(vx), "f"(vy));
                unsigned be = __ballot_sync(FULL, s0);
                unsigned bo = __ballot_sync(FULL, s1);
                if (lane == 0) {
                    unsigned w0 = expand16(be) | (expand16(bo) << 1);
                    unsigned w1 = expand16(be >> 16) | (expand16(bo >> 16) << 1);
                    *(unsigned long long*)&g_s1mask[t][rowA][2 * ch] =
                        (unsigned long long)w0 | ((unsigned long long)w1 << 32);
                    __threadfence();                       // release mask write
                    atomicAdd(&g_rowcnt[t][rowA], 1);      // publish (RED)
                }
            }
            // LIF row B
            if (hasB) {
                float ax, ay, ix, iy, vx, vy;
                asm("mov.b64 {%0,%1}, %2;" : "=f"(ax), "=f"(ay) : "l"(accB));
                asm("mov.b64 {%0,%1}, %2;" : "=f"(ix), "=f"(iy) : "l"(Ib));
                asm("mov.b64 {%0,%1}, %2;" : "=f"(vx), "=f"(vy) : "l"(Vb));
                ix = ALPHA * ix + ax;  iy = ALPHA * iy + ay;
                float vpx = BETA * vx + OMB * ix, vpy = BETA * vy + OMB * iy;
                bool s0 = vpx > 1.0f, s1 = vpy > 1.0f;
                vx = s0 ? 0.f : vpx;  vy = s1 ? 0.f : vpy;
                asm("mov.b64 %0, {%1,%2};" : "=l"(Ib) : "f"(ix), "f"(iy));
                asm("mov.b64 %0, {%1,%2};" : "=l"(Vb) : "f"(vx), "f"(vy));
                unsigned be = __ballot_sync(FULL, s0);
                unsigned bo = __ballot_sync(FULL, s1);
                if (lane == 0) {
                    unsigned w0 = expand16(be) | (expand16(bo) << 1);
                    unsigned w1 = expand16(be >> 16) | (expand16(bo >> 16) << 1);
                    *(unsigned long long*)&g_s1mask[t][rowB][2 * ch] =
                        (unsigned long long)w0 | ((unsigned long long)w1 << 32);
                    __threadfence();
                    atomicAdd(&g_rowcnt[t][rowB], 1);
                }
            }
            // NO block-level synchronization: warps free-run to next step
        }
    } else {
        // ===== layer 2 (consumer, free-running warps): 32-col chunk, warp = one row =====
        int bi  = bx - NB_L1;
        int ch  = bi & (N_CH2 - 1);
        int rep = bi >> 3;
        int jb  = ch * 32;
        for (int k = warp; k < D1 + 1; k += 32)
            tile[k * 32 + lane] = g_Wt2[k * D2 + jb + lane];
        unsigned* mylist = (unsigned*)((char*)tile + (D1 + 1) * 32 * 4) + warp * 520;
        int row = rep * 32 + warp;
        float I = 0.f, V = 0.f;
        const char* tb = (const char*)tile;
        int lane4 = lane << 2;
        __syncthreads();                          // tile ready; warps free-run

        #pragma unroll 1
        for (int t = 1; t < T_STEPS; ++t) {
            // wait for this row's 16 chunk publications at step t-1
            if (lane == 0) {
                volatile int* rc = &g_rowcnt[t - 1][row];
                if (*rc < N_CH1) {
                    while (*rc < N_CH1) __nanosleep(40);
                }
                __threadfence();                  // acquire
            }
            __syncwarp();

            unsigned mword = __ldcg(&g_s1mask[t - 1][row][lane]);
            float acc = 0.f;
            #pragma unroll 1
            for (int p = 0; p < 2; ++p) {
                unsigned wv = __shfl_sync(FULL, mword, (p << 4) + (lane >> 1));
                unsigned bits = (wv >> ((lane & 1) << 4)) & 0xffffu;
                int cnt = __popc(bits);
                int incl = cnt;
                #pragma unroll
                for (int o = 1; o < 32; o <<= 1) {
                    int v = __shfl_up_sync(FULL, incl, o);
                    if (lane >= o) incl += v;
                }
                int base  = incl - cnt;
                int total = __shfl_sync(FULL, incl, 31);
                int kb = (((p << 4) + (lane >> 1)) << 5) + ((lane & 1) << 4);
                int off = base;
                while (bits) {
                    int b = __ffs(bits) - 1;
                    bits &= bits - 1;
                    mylist[off++] = (unsigned)((kb + b) << 7);   // byte offset k*128
                }
                int totp = (total + 3) & ~3;
                for (int q = total + lane; q < totp; q += 32)
                    mylist[q] = (unsigned)(D1 << 7);             // zero-row pad
                __syncwarp();

                #pragma unroll 1
                for (int i = 0; i < totp; i += 4) {
                    uint4 o4 = *(const uint4*)(mylist + i);      // LDS.128 broadcast
                    acc += *(const float*)(tb + o4.x + lane4);
                    acc += *(const float*)(tb + o4.y + lane4);
                    acc += *(const float*)(tb + o4.z + lane4);
                    acc += *(const float*)(tb + o4.w + lane4);
                }
                __syncwarp();
            }

            I = ALPHA * I + acc;
            float Vp = BETA * V + OMB * I;
            bool s = Vp > 1.0f;
            V = s ? 0.f : Vp;
            out[t * (BATCH * D2) + row * D2 + jb + lane] = s ? 1.0f : 0.0f;
        }
    }
}

// ---------------- launch ----------------
extern "C" void kernel_launch(void* const* d_in, const int* in_sizes, int n_in,
                              void* d_out, int out_size) {
    const float *x = nullptr, *W1 = nullptr, *W2 = nullptr;
    for (int i = 0; i < n_in; ++i) {
        if      (in_sizes[i] == T_STEPS * BATCH * D0) x  = (const float*)d_in[i];
        else if (in_sizes[i] == D1 * D0)              W1 = (const float*)d_in[i];
        else if (in_sizes[i] == D2 * D1)              W2 = (const float*)d_in[i];
    }
    float* out = (float*)d_out;

    static int smem_set = 0;
    if (!smem_set) {
        cudaFuncSetAttribute(snn_persistent,
                             cudaFuncAttributeMaxDynamicSharedMemorySize, SMEM_BYTES);
        smem_set = 1;
    }

    prep_all<<<NB_PREP, 256>>>(x, W1, W2, out);
    snn_persistent<<<NBLOCKS, NT, SMEM_BYTES>>>(out);
}